// round 13
// baseline (speedup 1.0000x reference)
#include <cuda_runtime.h>
#include <cuda_bf16.h>
#include <cuda_fp16.h>
#include <cstdint>

// Problem constants (from reference): T=2, N=50000, E=800000, C=128
#define TT 2
#define MAXN 50000
#define MAXE 800000
#define CDIM 128

// Scratch (device globals: allocation-free rule). Everything batched over 2N/2E.
__device__ uint2  g_h[TT * MAXN * 32];          // 25.6 MB (GEMM product, fp16 rows, 2N)
__device__ float4 g_agg[TT * MAXN * (CDIM/4)];  // 51.2 MB (conv1 aggregation, fp32, 2N)
__device__ float  g_dinv[TT * MAXN];            // rsqrt(1 + deg)
__device__ int    g_hist[TT * MAXN];            // per-dst degree histogram
__device__ int    g_rowptr[TT * MAXN + 1];      // CSR row offsets (concatenated)
__device__ int    g_cursor[TT * MAXN];          // fill cursors for permute
__device__ int2   g_csr_sw[TT * MAXE];          // {global src id, dinv[src] bits}
__device__ int    g_bsum[128];                  // per-1024-chunk sums for scan
__device__ int    g_is64;                       // 1 if input edge dtype is int64
__device__ __nv_bfloat16 g_wh[2][CDIM * CDIM];  // pre-split W (high)
__device__ __nv_bfloat16 g_wl[2][CDIM * CDIM];  // pre-split W (low)

// ---------------------------------------------------------------------------
// Edge-index dtype detection (raw buffer may be int32 or int64)
// ---------------------------------------------------------------------------
__global__ void k_detect(const unsigned int* __restrict__ raw, int total_elems) {
    if (blockIdx.x == 0 && threadIdx.x == 0) {
        int n = total_elems < 64 ? total_elems : 64;
        int all0 = 1;
        for (int i = 0; i < n; i++)
            if (raw[2 * i + 1] != 0u) { all0 = 0; break; }
        g_is64 = all0;
    }
}

__device__ __forceinline__ int load_idx(const unsigned int* raw, int pos, int is64) {
    return is64 ? (int)raw[2 * (size_t)pos] : (int)raw[pos];
}

// ---------------------------------------------------------------------------
// W split: W (f32) -> Wh + Wl (bf16), done once per weight matrix.
// ---------------------------------------------------------------------------
__global__ void k_wsplit(const float* __restrict__ W, __nv_bfloat16* __restrict__ H,
                         __nv_bfloat16* __restrict__ L) {
    const int i = blockIdx.x * blockDim.x + threadIdx.x;
    const float v = W[i];
    const __nv_bfloat16 h = __float2bfloat16(v);
    H[i] = h;
    L[i] = __float2bfloat16(v - __bfloat162float(h));
}

// ---------------------------------------------------------------------------
// Batched CSR build (both timesteps)
// ---------------------------------------------------------------------------
__global__ void k_zero(int* p, int n) {
    int i = blockIdx.x * blockDim.x + threadIdx.x;
    if (i < n) p[i] = 0;
}

__global__ void k_hist2(int* __restrict__ hist, const unsigned int* __restrict__ raw,
                        int E, int N) {
    int i = blockIdx.x * blockDim.x + threadIdx.x;
    if (i >= 2 * E) return;
    const int is64 = g_is64;
    const int t = (i >= E) ? 1 : 0;
    const int eid = i - t * E;
    const int d = load_idx(raw, t * 2 * E + E + eid, is64);
    atomicAdd(&hist[t * N + d], 1);
}

__global__ __launch_bounds__(256) void k_bsum(const int* __restrict__ hist,
                                              int* __restrict__ bsum, int n) {
    __shared__ int ws[8];
    const int tid = threadIdx.x;
    const int base = blockIdx.x * 1024;
    int s = 0;
#pragma unroll
    for (int k = 0; k < 4; k++) {
        int i = base + k * 256 + tid;
        if (i < n) s += hist[i];
    }
#pragma unroll
    for (int o = 16; o; o >>= 1) s += __shfl_xor_sync(0xffffffffu, s, o);
    if ((tid & 31) == 0) ws[tid >> 5] = s;
    __syncthreads();
    if (tid < 32) {
        int v = (tid < 8) ? ws[tid] : 0;
#pragma unroll
        for (int o = 4; o; o >>= 1) v += __shfl_xor_sync(0xffffffffu, v, o);
        if (tid == 0) bsum[blockIdx.x] = v;
    }
}

__global__ __launch_bounds__(128) void k_scanb(int* __restrict__ bsum,
                                               int* __restrict__ rowptr,
                                               int nb, int n2) {
    __shared__ int ws[4];
    const int tid = threadIdx.x, lane = tid & 31, wid = tid >> 5;
    int v = (tid < nb) ? bsum[tid] : 0;
    int x = v;
#pragma unroll
    for (int o = 1; o < 32; o <<= 1) {
        int u = __shfl_up_sync(0xffffffffu, x, o);
        if (lane >= o) x += u;
    }
    if (lane == 31) ws[wid] = x;
    __syncthreads();
    if (wid == 0) {
        int wv = (lane < 4) ? ws[lane] : 0;
        int y = wv;
#pragma unroll
        for (int o = 1; o < 4; o <<= 1) {
            int u = __shfl_up_sync(0xffffffffu, y, o);
            if (lane >= o) y += u;
        }
        if (lane < 4) ws[lane] = y - wv;
    }
    __syncthreads();
    const int excl = x - v + ws[wid];
    if (tid < nb) bsum[tid] = excl;
    if (tid == nb - 1) rowptr[n2] = excl + v;
}

__global__ __launch_bounds__(256) void k_rowptr(const int* __restrict__ hist,
                                                const int* __restrict__ boff,
                                                int* __restrict__ rowptr,
                                                int* __restrict__ cursor,
                                                float* __restrict__ dinv, int n) {
    __shared__ int wsum[8];
    const int tid = threadIdx.x, lane = tid & 31, wid = tid >> 5;
    const int i0 = blockIdx.x * 1024 + tid * 4;
    int v0 = (i0     < n) ? hist[i0]     : 0;
    int v1 = (i0 + 1 < n) ? hist[i0 + 1] : 0;
    int v2 = (i0 + 2 < n) ? hist[i0 + 2] : 0;
    int v3 = (i0 + 3 < n) ? hist[i0 + 3] : 0;
    const int t = v0 + v1 + v2 + v3;
    int x = t;
#pragma unroll
    for (int o = 1; o < 32; o <<= 1) {
        int u = __shfl_up_sync(0xffffffffu, x, o);
        if (lane >= o) x += u;
    }
    if (lane == 31) wsum[wid] = x;
    __syncthreads();
    if (wid == 0) {
        int wv = (lane < 8) ? wsum[lane] : 0;
        int y = wv;
#pragma unroll
        for (int o = 1; o < 8; o <<= 1) {
            int u = __shfl_up_sync(0xffffffffu, y, o);
            if (lane >= o) y += u;
        }
        if (lane < 8) wsum[lane] = y - wv;
    }
    __syncthreads();
    int e0 = (x - t) + wsum[wid] + boff[blockIdx.x];
    int e1 = e0 + v0, e2 = e1 + v1, e3 = e2 + v2;
    if (i0     < n) { rowptr[i0]     = e0; cursor[i0]     = e0; dinv[i0]     = rsqrtf(1.0f + (float)v0); }
    if (i0 + 1 < n) { rowptr[i0 + 1] = e1; cursor[i0 + 1] = e1; dinv[i0 + 1] = rsqrtf(1.0f + (float)v1); }
    if (i0 + 2 < n) { rowptr[i0 + 2] = e2; cursor[i0 + 2] = e2; dinv[i0 + 2] = rsqrtf(1.0f + (float)v2); }
    if (i0 + 3 < n) { rowptr[i0 + 3] = e3; cursor[i0 + 3] = e3; dinv[i0 + 3] = rsqrtf(1.0f + (float)v3); }
}

// Permute: store {global src, dinv[src]} per CSR slot (saves a gather later).
__global__ void k_permute2(const unsigned int* __restrict__ raw, int* __restrict__ cursor,
                           int2* __restrict__ csr_sw, const float* __restrict__ dinv,
                           int E, int N) {
    int i = blockIdx.x * blockDim.x + threadIdx.x;
    if (i >= 2 * E) return;
    const int is64 = g_is64;
    const int t = (i >= E) ? 1 : 0;
    const int eid = i - t * E;
    const int s = load_idx(raw, t * 2 * E + eid, is64) + t * N;
    const int d = load_idx(raw, t * 2 * E + E + eid, is64);
    const int pos = atomicAdd(&cursor[t * N + d], 1);
    csr_sw[pos] = make_int2(s, __float_as_int(__ldg(&dinv[s])));
}

// ---------------------------------------------------------------------------
// Tensor-core GEMM: Yh[n,128] (fp16) = f(X)[n,128] (fp32) @ W[128,128]
// bf16 2-way split (3 MMA terms). W pre-split in global. M-tile 64.
// ---------------------------------------------------------------------------
#define SPAD 136
#define GEMM_SMEM ((2 * 64 + 2 * 128) * SPAD * 2)

__device__ __forceinline__ void store_split_a(__nv_bfloat16* H, __nv_bfloat16* L,
                                              int off, float4 v) {
    __nv_bfloat16 h0 = __float2bfloat16(v.x);
    __nv_bfloat16 h1 = __float2bfloat16(v.y);
    __nv_bfloat16 h2 = __float2bfloat16(v.z);
    __nv_bfloat16 h3 = __float2bfloat16(v.w);
    __nv_bfloat16 l0 = __float2bfloat16(v.x - __bfloat162float(h0));
    __nv_bfloat16 l1 = __float2bfloat16(v.y - __bfloat162float(h1));
    __nv_bfloat16 l2 = __float2bfloat16(v.z - __bfloat162float(h2));
    __nv_bfloat16 l3 = __float2bfloat16(v.w - __bfloat162float(h3));
    uint2 ph, pl;
    ph.x = (uint32_t)__bfloat16_as_ushort(h0) | ((uint32_t)__bfloat16_as_ushort(h1) << 16);
    ph.y = (uint32_t)__bfloat16_as_ushort(h2) | ((uint32_t)__bfloat16_as_ushort(h3) << 16);
    pl.x = (uint32_t)__bfloat16_as_ushort(l0) | ((uint32_t)__bfloat16_as_ushort(l1) << 16);
    pl.y = (uint32_t)__bfloat16_as_ushort(l2) | ((uint32_t)__bfloat16_as_ushort(l3) << 16);
    *reinterpret_cast<uint2*>(H + off) = ph;
    *reinterpret_cast<uint2*>(L + off) = pl;
}

#define LDSM_X4(r0, r1, r2, r3, addr)                                          \
    asm volatile("ldmatrix.sync.aligned.m8n8.x4.shared.b16 {%0,%1,%2,%3}, [%4];" \
                 : "=r"(r0), "=r"(r1), "=r"(r2), "=r"(r3) : "r"(addr))

#define LDSM_X4T(r0, r1, r2, r3, addr)                                         \
    asm volatile("ldmatrix.sync.aligned.m8n8.x4.trans.shared.b16 {%0,%1,%2,%3}, [%4];" \
                 : "=r"(r0), "=r"(r1), "=r"(r2), "=r"(r3) : "r"(addr))

#define MMA16816(C, a0, a1, a2, a3, b0, b1)                                    \
    asm volatile("mma.sync.aligned.m16n8k16.row.col.f32.bf16.bf16.f32 "        \
                 "{%0,%1,%2,%3}, {%4,%5,%6,%7}, {%8,%9}, {%0,%1,%2,%3};"       \
                 : "+f"(C[0]), "+f"(C[1]), "+f"(C[2]), "+f"(C[3])              \
                 : "r"(a0), "r"(a1), "r"(a2), "r"(a3), "r"(b0), "r"(b1))

__global__ __launch_bounds__(256) void k_gemm_mma(
    const float* __restrict__ X,
    const __nv_bfloat16* __restrict__ Whg, const __nv_bfloat16* __restrict__ Wlg,
    const float* __restrict__ bias, __half* __restrict__ Y, int nrows, int mode)
{
    extern __shared__ __nv_bfloat16 sm[];
    __nv_bfloat16* Ah = sm;                       //  64 x SPAD
    __nv_bfloat16* Al = Ah + 64 * SPAD;           //  64 x SPAD
    __nv_bfloat16* Wh = Al + 64 * SPAD;           // 128 x SPAD
    __nv_bfloat16* Wl = Wh + 128 * SPAD;          // 128 x SPAD

    const int tid = threadIdx.x;
    const int lane = tid & 31, wid = tid >> 5;
    const int rowBase = blockIdx.x * 64;

#pragma unroll
    for (int it = 0; it < 8; it++) {
        const int idx = it * 256 + tid;
        const int row = idx >> 4;
        const int c8  = (idx & 15) * 8;
        *reinterpret_cast<uint4*>(Wh + row * SPAD + c8) =
            reinterpret_cast<const uint4*>(Whg)[idx];
        *reinterpret_cast<uint4*>(Wl + row * SPAD + c8) =
            reinterpret_cast<const uint4*>(Wlg)[idx];
    }
#pragma unroll
    for (int it = 0; it < 8; it++) {
        const int idx = it * 256 + tid;
        const int row = idx >> 5;
        const int c4  = idx & 31;
        const int grow = rowBase + row;
        float4 v = make_float4(0.f, 0.f, 0.f, 0.f);
        if (grow < nrows) v = reinterpret_cast<const float4*>(X)[grow * 32 + c4];
        if (mode == 1) {
            const float4 b = reinterpret_cast<const float4*>(bias)[c4];
            v.x = fmaxf(v.x + b.x, 0.f);
            v.y = fmaxf(v.y + b.y, 0.f);
            v.z = fmaxf(v.z + b.z, 0.f);
            v.w = fmaxf(v.w + b.w, 0.f);
        }
        store_split_a(Ah, Al, row * SPAD + c4 * 4, v);
    }
    __syncthreads();

    const uint32_t sb = (uint32_t)__cvta_generic_to_shared(sm);
    const uint32_t AHALF = 64 * SPAD * 2;
    const uint32_t WBASE = 2u * AHALF;
    const uint32_t WHALF = 128 * SPAD * 2;
    const int sub = lane >> 3, li = lane & 7;
    const int wm = wid & 3;
    const int wn = wid >> 2;
    const int arow = wm * 16 + ((sub & 1) << 3) + li;
    const int acol0 = (sub >> 1) << 3;
    const int bkrow0 = ((sub & 1) << 3) + li;
    const int bncol0 = wn * 64 + ((sub >> 1) << 3);

    float acc[8][4];
#pragma unroll
    for (int t = 0; t < 8; t++)
#pragma unroll
        for (int c = 0; c < 4; c++) acc[t][c] = 0.f;

    for (int k0 = 0; k0 < 128; k0 += 16) {
        uint32_t aaddr = sb + (uint32_t)((arow * SPAD + k0 + acol0) * 2);
        uint32_t ah0, ah1, ah2, ah3, al0, al1, al2, al3;
        LDSM_X4(ah0, ah1, ah2, ah3, aaddr);
        LDSM_X4(al0, al1, al2, al3, aaddr + AHALF);

#pragma unroll
        for (int np = 0; np < 4; np++) {
            uint32_t baddr = sb + WBASE +
                (uint32_t)(((k0 + bkrow0) * SPAD + np * 16 + bncol0) * 2);
            uint32_t bh0, bh1, bh2, bh3, bl0, bl1, bl2, bl3;
            LDSM_X4T(bh0, bh1, bh2, bh3, baddr);
            LDSM_X4T(bl0, bl1, bl2, bl3, baddr + WHALF);
            const int t0 = np * 2, t1 = t0 + 1;
            MMA16816(acc[t0], ah0, ah1, ah2, ah3, bh0, bh1);
            MMA16816(acc[t0], al0, al1, al2, al3, bh0, bh1);
            MMA16816(acc[t0], ah0, ah1, ah2, ah3, bl0, bl1);
            MMA16816(acc[t1], ah0, ah1, ah2, ah3, bh2, bh3);
            MMA16816(acc[t1], al0, al1, al2, al3, bh2, bh3);
            MMA16816(acc[t1], ah0, ah1, ah2, ah3, bl2, bl3);
        }
    }

    const int r0 = rowBase + wm * 16 + (lane >> 2);
    const int c0 = wn * 64 + (lane & 3) * 2;
#pragma unroll
    for (int nt = 0; nt < 8; nt++) {
        const int col = c0 + nt * 8;
        if (r0 < nrows)
            *reinterpret_cast<__half2*>(&Y[r0 * 128 + col]) =
                __floats2half2_rn(acc[nt][0], acc[nt][1]);
        if (r0 + 8 < nrows)
            *reinterpret_cast<__half2*>(&Y[(r0 + 8) * 128 + col]) =
                __floats2half2_rn(acc[nt][2], acc[nt][3]);
    }
}

// ---------------------------------------------------------------------------
// CSR gather v2: one warp per node, 2 edges in flight (16 lanes each),
// uint4 (16B) row loads, packed {src, dinv[src]} CSR slots.
// MODE 1 additionally fuses the importance head for nodes >= nN.
// ---------------------------------------------------------------------------
#define CVT_FMA(ACC, R, W)                                                     \
    {                                                                          \
        const __half2* hp_ = reinterpret_cast<const __half2*>(&R);             \
        float2 f_;                                                             \
        f_ = __half22float2(hp_[0]);                                           \
        ACC[0] = fmaf(f_.x, W, ACC[0]); ACC[1] = fmaf(f_.y, W, ACC[1]);        \
        f_ = __half22float2(hp_[1]);                                           \
        ACC[2] = fmaf(f_.x, W, ACC[2]); ACC[3] = fmaf(f_.y, W, ACC[3]);        \
        f_ = __half22float2(hp_[2]);                                           \
        ACC[4] = fmaf(f_.x, W, ACC[4]); ACC[5] = fmaf(f_.y, W, ACC[5]);        \
        f_ = __half22float2(hp_[3]);                                           \
        ACC[6] = fmaf(f_.x, W, ACC[6]); ACC[7] = fmaf(f_.y, W, ACC[7]);        \
    }

template <int MODE>
__global__ __launch_bounds__(256) void k_gather(
    const uint4* __restrict__ h, float4* __restrict__ out,
    const int* __restrict__ rowptr, const int2* __restrict__ csr_sw,
    const float* __restrict__ dinv, const float* __restrict__ bias, int n,
    const float* __restrict__ Wc, const float* __restrict__ bc,
    float* __restrict__ imp, int nN)
{
    const int node = blockIdx.x * 8 + (threadIdx.x >> 5);
    if (node >= n) return;
    const int lane = threadIdx.x & 31;
    const int half = lane >> 4;       // which of the 2 concurrent edges
    const int fl   = lane & 15;       // feature slot: features fl*8 .. fl*8+7

    const float dd = __ldg(&dinv[node]);
    const int js = __ldg(&rowptr[node]);
    const int je = __ldg(&rowptr[node + 1]);

    float acc[8] = {0.f, 0.f, 0.f, 0.f, 0.f, 0.f, 0.f, 0.f};
    float acc2[8] = {0.f, 0.f, 0.f, 0.f, 0.f, 0.f, 0.f, 0.f};

    // self-loop on half 0
    if (half == 0) {
        const uint4 r = __ldg(&h[(size_t)node * 16 + fl]);
        const float sl = dd * dd;
        CVT_FMA(acc, r, sl);
    }

    int j = js + half;
    for (; j + 2 < je; j += 4) {
        const int2 sw0 = __ldg(&csr_sw[j]);
        const int2 sw1 = __ldg(&csr_sw[j + 2]);
        const float w0 = dd * __int_as_float(sw0.y);
        const float w1 = dd * __int_as_float(sw1.y);
        const uint4 r0 = __ldg(&h[(size_t)sw0.x * 16 + fl]);
        const uint4 r1 = __ldg(&h[(size_t)sw1.x * 16 + fl]);
        CVT_FMA(acc, r0, w0);
        CVT_FMA(acc2, r1, w1);
    }
    if (j < je) {
        const int2 sw0 = __ldg(&csr_sw[j]);
        const float w0 = dd * __int_as_float(sw0.y);
        const uint4 r0 = __ldg(&h[(size_t)sw0.x * 16 + fl]);
        CVT_FMA(acc, r0, w0);
    }
#pragma unroll
    for (int i = 0; i < 8; i++) acc[i] += acc2[i];
    // combine the two edge-halves (lanes L and L+16 hold same feature slots)
#pragma unroll
    for (int i = 0; i < 8; i++) acc[i] += __shfl_xor_sync(0xffffffffu, acc[i], 16);

    if (MODE == 1) {
        const float4 b0 = __ldg(&reinterpret_cast<const float4*>(bias)[fl * 2]);
        const float4 b1 = __ldg(&reinterpret_cast<const float4*>(bias)[fl * 2 + 1]);
        acc[0] += b0.x; acc[1] += b0.y; acc[2] += b0.z; acc[3] += b0.w;
        acc[4] += b1.x; acc[5] += b1.y; acc[6] += b1.z; acc[7] += b1.w;
    }

    if (half == 0) {
        out[node * 32 + fl * 2]     = make_float4(acc[0], acc[1], acc[2], acc[3]);
        out[node * 32 + fl * 2 + 1] = make_float4(acc[4], acc[5], acc[6], acc[7]);
    }

    // fused importance head for t=1 nodes (final timestep output)
    if (MODE == 1 && node >= nN) {
        const float4 w0 = __ldg(&reinterpret_cast<const float4*>(Wc)[fl * 2]);
        const float4 w1 = __ldg(&reinterpret_cast<const float4*>(Wc)[fl * 2 + 1]);
        float s = acc[0] * w0.x + acc[1] * w0.y + acc[2] * w0.z + acc[3] * w0.w
                + acc[4] * w1.x + acc[5] * w1.y + acc[6] * w1.z + acc[7] * w1.w;
#pragma unroll
        for (int o = 8; o; o >>= 1) s += __shfl_xor_sync(0xffffffffu, s, o);
        if (lane == 0) imp[node - nN] = s + __ldg(bc);
    }
}

// ---------------------------------------------------------------------------
// Launch — batched over both timesteps; CSR build overlapped with GEMM1
// ---------------------------------------------------------------------------
extern "C" void kernel_launch(void* const* d_in, const int* in_sizes, int n_in,
                              void* d_out, int out_size)
{
    const float*        x_seq = (const float*)d_in[0];        // [2N, 128] contiguous
    const unsigned int* eraw  = (const unsigned int*)d_in[1]; // [T, 2, E] int32 or int64
    const float*        W1    = (const float*)d_in[2];
    const float*        b1    = (const float*)d_in[3];
    const float*        W2    = (const float*)d_in[4];
    const float*        b2    = (const float*)d_in[5];
    const float*        Wc    = (const float*)d_in[6];
    const float*        bc    = (const float*)d_in[7];

    const int N = in_sizes[0] / (TT * CDIM);
    const int E = in_sizes[1] / (TT * 2);
    const int totalE = TT * 2 * E;
    const int n2 = TT * N;

    float* out  = (float*)d_out;
    float* imp  = out;          // [N]
    float* outs = out + N;      // [2N,128] contiguous (out_t0 then out_t1)

    uint2* dh;  float4* dagg;  float* ddinv;
    int* dhist;  int* drowptr;  int* dcursor;  int2* dcsr;  int* dbsum;
    __nv_bfloat16* dwh; __nv_bfloat16* dwl;
    cudaGetSymbolAddress((void**)&dh,      g_h);
    cudaGetSymbolAddress((void**)&dagg,    g_agg);
    cudaGetSymbolAddress((void**)&ddinv,   g_dinv);
    cudaGetSymbolAddress((void**)&dhist,   g_hist);
    cudaGetSymbolAddress((void**)&drowptr, g_rowptr);
    cudaGetSymbolAddress((void**)&dcursor, g_cursor);
    cudaGetSymbolAddress((void**)&dcsr,    g_csr_sw);
    cudaGetSymbolAddress((void**)&dbsum,   g_bsum);
    cudaGetSymbolAddress((void**)&dwh,     g_wh);
    cudaGetSymbolAddress((void**)&dwl,     g_wl);

    static bool s_init = false;
    static cudaStream_t s_side = nullptr;
    static cudaEvent_t ev_fork = nullptr, ev_join = nullptr;
    if (!s_init) {
        cudaFuncSetAttribute(k_gemm_mma, cudaFuncAttributeMaxDynamicSharedMemorySize,
                             GEMM_SMEM);
        if (cudaStreamCreateWithFlags(&s_side, cudaStreamNonBlocking) != cudaSuccess)
            s_side = nullptr;
        if (s_side) {
            cudaEventCreateWithFlags(&ev_fork, cudaEventDisableTiming);
            cudaEventCreateWithFlags(&ev_join, cudaEventDisableTiming);
        }
        s_init = true;
    }

    const int TPB = 256;
    const int gGemm = (n2 + 63) / 64;
    const int gGath = (n2 + 7) / 8;
    const int g2E   = (2 * E + TPB - 1) / TPB;
    const int g2N   = (n2 + TPB - 1) / TPB;
    const int nb    = (n2 + 1023) / 1024;

    const bool fork = (s_side != nullptr);
    cudaStream_t sc = fork ? s_side : (cudaStream_t)0;

    // Edge dtype probe (main stream), then fork the CSR chain behind it.
    // NOTE: every side-stream launch must come AFTER the fork event so it is
    // part of the captured graph (a pre-fork launch runs eagerly and is lost
    // on replay -> stale hist -> OOB).
    k_detect<<<1, 32>>>(eraw, totalE);
    if (fork) {
        cudaEventRecord(ev_fork, 0);
        cudaStreamWaitEvent(s_side, ev_fork, 0);
    }

    // --- CSR build chain (side stream, fully captured) ---
    k_zero<<<g2N, TPB, 0, sc>>>(dhist, n2);
    k_hist2<<<g2E, TPB, 0, sc>>>(dhist, eraw, E, N);
    k_bsum<<<nb, TPB, 0, sc>>>(dhist, dbsum, n2);
    k_scanb<<<1, 128, 0, sc>>>(dbsum, drowptr, nb, n2);
    k_rowptr<<<nb, TPB, 0, sc>>>(dhist, dbsum, drowptr, dcursor, ddinv, n2);
    k_permute2<<<g2E, TPB, 0, sc>>>(eraw, dcursor, dcsr, ddinv, E, N);
    if (fork) cudaEventRecord(ev_join, s_side);

    // --- Main stream: W splits + conv1 GEMM (independent of CSR) ---
    k_wsplit<<<64, TPB>>>(W1, dwh, dwl);
    k_wsplit<<<64, TPB>>>(W2, dwh + CDIM * CDIM, dwl + CDIM * CDIM);
    k_gemm_mma<<<gGemm, TPB, GEMM_SMEM>>>(x_seq, dwh, dwl, b1, (__half*)dh, n2, 0);

    if (fork) cudaStreamWaitEvent(0, ev_join, 0);

    // conv1 aggregation, conv2 GEMM, conv2 aggregation + fused importance.
    k_gather<0><<<gGath, TPB>>>((const uint4*)dh, dagg, drowptr, dcsr, ddinv,
                                b1, n2, Wc, bc, imp, N);
    k_gemm_mma<<<gGemm, TPB, GEMM_SMEM>>>((const float*)dagg, dwh + CDIM * CDIM,
                                          dwl + CDIM * CDIM, b1, (__half*)dh, n2, 1);
    k_gather<1><<<gGath, TPB>>>((const uint4*)dh, (float4*)outs, drowptr, dcsr, ddinv,
                                b2, n2, Wc, bc, imp, N);
}

// round 14
// speedup vs baseline: 1.0149x; 1.0149x over previous
#include <cuda_runtime.h>
#include <cuda_bf16.h>
#include <cuda_fp16.h>
#include <cstdint>

// Problem constants (from reference): T=2, N=50000, E=800000, C=128
#define TT 2
#define MAXN 50000
#define MAXE 800000
#define CDIM 128

// Scratch (device globals: allocation-free rule). Everything batched over 2N/2E.
__device__ uint2  g_h[TT * MAXN * 32];          // 25.6 MB (GEMM product, fp16 rows, 2N)
__device__ float4 g_agg[TT * MAXN * (CDIM/4)];  // 51.2 MB (conv1 aggregation, fp32, 2N)
__device__ float  g_dinv[TT * MAXN];            // rsqrt(1 + deg)
__device__ int    g_hist[TT * MAXN];            // per-dst degree histogram
__device__ int    g_rowptr[TT * MAXN + 1];      // CSR row offsets (concatenated)
__device__ int    g_cursor[TT * MAXN];          // fill cursors for permute
__device__ int2   g_csr_sw[TT * MAXE];          // {global src id, dinv[src] bits}
__device__ int    g_bsum[128];                  // per-1024-chunk sums for scan
__device__ int    g_is64;                       // 1 if input edge dtype is int64
__device__ __nv_bfloat16 g_wh[2][CDIM * CDIM];  // pre-split W (high)
__device__ __nv_bfloat16 g_wl[2][CDIM * CDIM];  // pre-split W (low)

// ---------------------------------------------------------------------------
// Edge-index dtype detection (raw buffer may be int32 or int64)
// ---------------------------------------------------------------------------
__global__ void k_detect(const unsigned int* __restrict__ raw, int total_elems) {
    if (blockIdx.x == 0 && threadIdx.x == 0) {
        int n = total_elems < 64 ? total_elems : 64;
        int all0 = 1;
        for (int i = 0; i < n; i++)
            if (raw[2 * i + 1] != 0u) { all0 = 0; break; }
        g_is64 = all0;
    }
}

__device__ __forceinline__ int load_idx(const unsigned int* raw, int pos, int is64) {
    return is64 ? (int)raw[2 * (size_t)pos] : (int)raw[pos];
}

// ---------------------------------------------------------------------------
// W split: W (f32) -> Wh + Wl (bf16), done once per weight matrix.
// ---------------------------------------------------------------------------
__global__ void k_wsplit(const float* __restrict__ W, __nv_bfloat16* __restrict__ H,
                         __nv_bfloat16* __restrict__ L) {
    const int i = blockIdx.x * blockDim.x + threadIdx.x;
    const float v = W[i];
    const __nv_bfloat16 h = __float2bfloat16(v);
    H[i] = h;
    L[i] = __float2bfloat16(v - __bfloat162float(h));
}

// ---------------------------------------------------------------------------
// Batched CSR build (both timesteps)
// ---------------------------------------------------------------------------
__global__ void k_zero(int* p, int n) {
    int i = blockIdx.x * blockDim.x + threadIdx.x;
    if (i < n) p[i] = 0;
}

__global__ void k_hist2(int* __restrict__ hist, const unsigned int* __restrict__ raw,
                        int E, int N) {
    int i = blockIdx.x * blockDim.x + threadIdx.x;
    if (i >= 2 * E) return;
    const int is64 = g_is64;
    const int t = (i >= E) ? 1 : 0;
    const int eid = i - t * E;
    const int d = load_idx(raw, t * 2 * E + E + eid, is64);
    atomicAdd(&hist[t * N + d], 1);
}

__global__ __launch_bounds__(256) void k_bsum(const int* __restrict__ hist,
                                              int* __restrict__ bsum, int n) {
    __shared__ int ws[8];
    const int tid = threadIdx.x;
    const int base = blockIdx.x * 1024;
    int s = 0;
#pragma unroll
    for (int k = 0; k < 4; k++) {
        int i = base + k * 256 + tid;
        if (i < n) s += hist[i];
    }
#pragma unroll
    for (int o = 16; o; o >>= 1) s += __shfl_xor_sync(0xffffffffu, s, o);
    if ((tid & 31) == 0) ws[tid >> 5] = s;
    __syncthreads();
    if (tid < 32) {
        int v = (tid < 8) ? ws[tid] : 0;
#pragma unroll
        for (int o = 4; o; o >>= 1) v += __shfl_xor_sync(0xffffffffu, v, o);
        if (tid == 0) bsum[blockIdx.x] = v;
    }
}

__global__ __launch_bounds__(128) void k_scanb(int* __restrict__ bsum,
                                               int* __restrict__ rowptr,
                                               int nb, int n2) {
    __shared__ int ws[4];
    const int tid = threadIdx.x, lane = tid & 31, wid = tid >> 5;
    int v = (tid < nb) ? bsum[tid] : 0;
    int x = v;
#pragma unroll
    for (int o = 1; o < 32; o <<= 1) {
        int u = __shfl_up_sync(0xffffffffu, x, o);
        if (lane >= o) x += u;
    }
    if (lane == 31) ws[wid] = x;
    __syncthreads();
    if (wid == 0) {
        int wv = (lane < 4) ? ws[lane] : 0;
        int y = wv;
#pragma unroll
        for (int o = 1; o < 4; o <<= 1) {
            int u = __shfl_up_sync(0xffffffffu, y, o);
            if (lane >= o) y += u;
        }
        if (lane < 4) ws[lane] = y - wv;
    }
    __syncthreads();
    const int excl = x - v + ws[wid];
    if (tid < nb) bsum[tid] = excl;
    if (tid == nb - 1) rowptr[n2] = excl + v;
}

__global__ __launch_bounds__(256) void k_rowptr(const int* __restrict__ hist,
                                                const int* __restrict__ boff,
                                                int* __restrict__ rowptr,
                                                int* __restrict__ cursor,
                                                float* __restrict__ dinv, int n) {
    __shared__ int wsum[8];
    const int tid = threadIdx.x, lane = tid & 31, wid = tid >> 5;
    const int i0 = blockIdx.x * 1024 + tid * 4;
    int v0 = (i0     < n) ? hist[i0]     : 0;
    int v1 = (i0 + 1 < n) ? hist[i0 + 1] : 0;
    int v2 = (i0 + 2 < n) ? hist[i0 + 2] : 0;
    int v3 = (i0 + 3 < n) ? hist[i0 + 3] : 0;
    const int t = v0 + v1 + v2 + v3;
    int x = t;
#pragma unroll
    for (int o = 1; o < 32; o <<= 1) {
        int u = __shfl_up_sync(0xffffffffu, x, o);
        if (lane >= o) x += u;
    }
    if (lane == 31) wsum[wid] = x;
    __syncthreads();
    if (wid == 0) {
        int wv = (lane < 8) ? wsum[lane] : 0;
        int y = wv;
#pragma unroll
        for (int o = 1; o < 8; o <<= 1) {
            int u = __shfl_up_sync(0xffffffffu, y, o);
            if (lane >= o) y += u;
        }
        if (lane < 8) wsum[lane] = y - wv;
    }
    __syncthreads();
    int e0 = (x - t) + wsum[wid] + boff[blockIdx.x];
    int e1 = e0 + v0, e2 = e1 + v1, e3 = e2 + v2;
    if (i0     < n) { rowptr[i0]     = e0; cursor[i0]     = e0; dinv[i0]     = rsqrtf(1.0f + (float)v0); }
    if (i0 + 1 < n) { rowptr[i0 + 1] = e1; cursor[i0 + 1] = e1; dinv[i0 + 1] = rsqrtf(1.0f + (float)v1); }
    if (i0 + 2 < n) { rowptr[i0 + 2] = e2; cursor[i0 + 2] = e2; dinv[i0 + 2] = rsqrtf(1.0f + (float)v2); }
    if (i0 + 3 < n) { rowptr[i0 + 3] = e3; cursor[i0 + 3] = e3; dinv[i0 + 3] = rsqrtf(1.0f + (float)v3); }
}

// Permute: store {global src, dinv[src]} per CSR slot (saves a gather later).
__global__ void k_permute2(const unsigned int* __restrict__ raw, int* __restrict__ cursor,
                           int2* __restrict__ csr_sw, const float* __restrict__ dinv,
                           int E, int N) {
    int i = blockIdx.x * blockDim.x + threadIdx.x;
    if (i >= 2 * E) return;
    const int is64 = g_is64;
    const int t = (i >= E) ? 1 : 0;
    const int eid = i - t * E;
    const int s = load_idx(raw, t * 2 * E + eid, is64) + t * N;
    const int d = load_idx(raw, t * 2 * E + E + eid, is64);
    const int pos = atomicAdd(&cursor[t * N + d], 1);
    csr_sw[pos] = make_int2(s, __float_as_int(__ldg(&dinv[s])));
}

// ---------------------------------------------------------------------------
// Tensor-core GEMM: Yh[n,128] (fp16) = f(X)[n,128] (fp32) @ W[128,128]
// bf16 2-way split (3 MMA terms). W pre-split in global. M-tile 64.
// ---------------------------------------------------------------------------
#define SPAD 136
#define GEMM_SMEM ((2 * 64 + 2 * 128) * SPAD * 2)

__device__ __forceinline__ void store_split_a(__nv_bfloat16* H, __nv_bfloat16* L,
                                              int off, float4 v) {
    __nv_bfloat16 h0 = __float2bfloat16(v.x);
    __nv_bfloat16 h1 = __float2bfloat16(v.y);
    __nv_bfloat16 h2 = __float2bfloat16(v.z);
    __nv_bfloat16 h3 = __float2bfloat16(v.w);
    __nv_bfloat16 l0 = __float2bfloat16(v.x - __bfloat162float(h0));
    __nv_bfloat16 l1 = __float2bfloat16(v.y - __bfloat162float(h1));
    __nv_bfloat16 l2 = __float2bfloat16(v.z - __bfloat162float(h2));
    __nv_bfloat16 l3 = __float2bfloat16(v.w - __bfloat162float(h3));
    uint2 ph, pl;
    ph.x = (uint32_t)__bfloat16_as_ushort(h0) | ((uint32_t)__bfloat16_as_ushort(h1) << 16);
    ph.y = (uint32_t)__bfloat16_as_ushort(h2) | ((uint32_t)__bfloat16_as_ushort(h3) << 16);
    pl.x = (uint32_t)__bfloat16_as_ushort(l0) | ((uint32_t)__bfloat16_as_ushort(l1) << 16);
    pl.y = (uint32_t)__bfloat16_as_ushort(l2) | ((uint32_t)__bfloat16_as_ushort(l3) << 16);
    *reinterpret_cast<uint2*>(H + off) = ph;
    *reinterpret_cast<uint2*>(L + off) = pl;
}

#define LDSM_X4(r0, r1, r2, r3, addr)                                          \
    asm volatile("ldmatrix.sync.aligned.m8n8.x4.shared.b16 {%0,%1,%2,%3}, [%4];" \
                 : "=r"(r0), "=r"(r1), "=r"(r2), "=r"(r3) : "r"(addr))

#define LDSM_X4T(r0, r1, r2, r3, addr)                                         \
    asm volatile("ldmatrix.sync.aligned.m8n8.x4.trans.shared.b16 {%0,%1,%2,%3}, [%4];" \
                 : "=r"(r0), "=r"(r1), "=r"(r2), "=r"(r3) : "r"(addr))

#define MMA16816(C, a0, a1, a2, a3, b0, b1)                                    \
    asm volatile("mma.sync.aligned.m16n8k16.row.col.f32.bf16.bf16.f32 "        \
                 "{%0,%1,%2,%3}, {%4,%5,%6,%7}, {%8,%9}, {%0,%1,%2,%3};"       \
                 : "+f"(C[0]), "+f"(C[1]), "+f"(C[2]), "+f"(C[3])              \
                 : "r"(a0), "r"(a1), "r"(a2), "r"(a3), "r"(b0), "r"(b1))

__global__ __launch_bounds__(256) void k_gemm_mma(
    const float* __restrict__ X,
    const __nv_bfloat16* __restrict__ Whg, const __nv_bfloat16* __restrict__ Wlg,
    const float* __restrict__ bias, __half* __restrict__ Y, int nrows, int mode)
{
    extern __shared__ __nv_bfloat16 sm[];
    __nv_bfloat16* Ah = sm;                       //  64 x SPAD
    __nv_bfloat16* Al = Ah + 64 * SPAD;           //  64 x SPAD
    __nv_bfloat16* Wh = Al + 64 * SPAD;           // 128 x SPAD
    __nv_bfloat16* Wl = Wh + 128 * SPAD;          // 128 x SPAD

    const int tid = threadIdx.x;
    const int lane = tid & 31, wid = tid >> 5;
    const int rowBase = blockIdx.x * 64;

#pragma unroll
    for (int it = 0; it < 8; it++) {
        const int idx = it * 256 + tid;
        const int row = idx >> 4;
        const int c8  = (idx & 15) * 8;
        *reinterpret_cast<uint4*>(Wh + row * SPAD + c8) =
            reinterpret_cast<const uint4*>(Whg)[idx];
        *reinterpret_cast<uint4*>(Wl + row * SPAD + c8) =
            reinterpret_cast<const uint4*>(Wlg)[idx];
    }
#pragma unroll
    for (int it = 0; it < 8; it++) {
        const int idx = it * 256 + tid;
        const int row = idx >> 5;
        const int c4  = idx & 31;
        const int grow = rowBase + row;
        float4 v = make_float4(0.f, 0.f, 0.f, 0.f);
        if (grow < nrows) v = reinterpret_cast<const float4*>(X)[grow * 32 + c4];
        if (mode == 1) {
            const float4 b = reinterpret_cast<const float4*>(bias)[c4];
            v.x = fmaxf(v.x + b.x, 0.f);
            v.y = fmaxf(v.y + b.y, 0.f);
            v.z = fmaxf(v.z + b.z, 0.f);
            v.w = fmaxf(v.w + b.w, 0.f);
        }
        store_split_a(Ah, Al, row * SPAD + c4 * 4, v);
    }
    __syncthreads();

    const uint32_t sb = (uint32_t)__cvta_generic_to_shared(sm);
    const uint32_t AHALF = 64 * SPAD * 2;
    const uint32_t WBASE = 2u * AHALF;
    const uint32_t WHALF = 128 * SPAD * 2;
    const int sub = lane >> 3, li = lane & 7;
    const int wm = wid & 3;
    const int wn = wid >> 2;
    const int arow = wm * 16 + ((sub & 1) << 3) + li;
    const int acol0 = (sub >> 1) << 3;
    const int bkrow0 = ((sub & 1) << 3) + li;
    const int bncol0 = wn * 64 + ((sub >> 1) << 3);

    float acc[8][4];
#pragma unroll
    for (int t = 0; t < 8; t++)
#pragma unroll
        for (int c = 0; c < 4; c++) acc[t][c] = 0.f;

    for (int k0 = 0; k0 < 128; k0 += 16) {
        uint32_t aaddr = sb + (uint32_t)((arow * SPAD + k0 + acol0) * 2);
        uint32_t ah0, ah1, ah2, ah3, al0, al1, al2, al3;
        LDSM_X4(ah0, ah1, ah2, ah3, aaddr);
        LDSM_X4(al0, al1, al2, al3, aaddr + AHALF);

#pragma unroll
        for (int np = 0; np < 4; np++) {
            uint32_t baddr = sb + WBASE +
                (uint32_t)(((k0 + bkrow0) * SPAD + np * 16 + bncol0) * 2);
            uint32_t bh0, bh1, bh2, bh3, bl0, bl1, bl2, bl3;
            LDSM_X4T(bh0, bh1, bh2, bh3, baddr);
            LDSM_X4T(bl0, bl1, bl2, bl3, baddr + WHALF);
            const int t0 = np * 2, t1 = t0 + 1;
            MMA16816(acc[t0], ah0, ah1, ah2, ah3, bh0, bh1);
            MMA16816(acc[t0], al0, al1, al2, al3, bh0, bh1);
            MMA16816(acc[t0], ah0, ah1, ah2, ah3, bl0, bl1);
            MMA16816(acc[t1], ah0, ah1, ah2, ah3, bh2, bh3);
            MMA16816(acc[t1], al0, al1, al2, al3, bh2, bh3);
            MMA16816(acc[t1], ah0, ah1, ah2, ah3, bl2, bl3);
        }
    }

    const int r0 = rowBase + wm * 16 + (lane >> 2);
    const int c0 = wn * 64 + (lane & 3) * 2;
#pragma unroll
    for (int nt = 0; nt < 8; nt++) {
        const int col = c0 + nt * 8;
        if (r0 < nrows)
            *reinterpret_cast<__half2*>(&Y[r0 * 128 + col]) =
                __floats2half2_rn(acc[nt][0], acc[nt][1]);
        if (r0 + 8 < nrows)
            *reinterpret_cast<__half2*>(&Y[(r0 + 8) * 128 + col]) =
                __floats2half2_rn(acc[nt][2], acc[nt][3]);
    }
}

// ---------------------------------------------------------------------------
// CSR gather (R11 shape + packed slots): one warp per node, uint2 (8B/lane)
// fp16 row loads, unroll x8 for MLP, {src, dinv[src]} packed CSR slots.
// MODE 1 adds bias b2 and fuses the importance head for nodes >= nN.
// ---------------------------------------------------------------------------
__device__ __forceinline__ float4 h4_to_f4(uint2 u) {
    const __half2 a = *reinterpret_cast<__half2*>(&u.x);
    const __half2 b = *reinterpret_cast<__half2*>(&u.y);
    const float2 fa = __half22float2(a), fb = __half22float2(b);
    return make_float4(fa.x, fa.y, fb.x, fb.y);
}

#define GFMA(A, V, W) \
    A.x = fmaf(V.x, W, A.x); A.y = fmaf(V.y, W, A.y); \
    A.z = fmaf(V.z, W, A.z); A.w = fmaf(V.w, W, A.w);

template <int MODE>
__global__ __launch_bounds__(256) void k_gather(
    const uint2* __restrict__ h, float4* __restrict__ out,
    const int* __restrict__ rowptr, const int2* __restrict__ csr_sw,
    const float* __restrict__ dinv, const float* __restrict__ bias, int n,
    const float* __restrict__ Wc, const float* __restrict__ bc,
    float* __restrict__ imp, int nN)
{
    const int node = blockIdx.x * 8 + (threadIdx.x >> 5);
    if (node >= n) return;
    const int lane = threadIdx.x & 31;

    const float dd = __ldg(&dinv[node]);
    const int js = __ldg(&rowptr[node]);
    const int je = __ldg(&rowptr[node + 1]);

    const float4 v = h4_to_f4(h[node * 32 + lane]);
    const float sl = dd * dd;
    float4 a0 = make_float4(v.x * sl, v.y * sl, v.z * sl, v.w * sl);
    float4 a1 = make_float4(0.f, 0.f, 0.f, 0.f);
    float4 a2 = make_float4(0.f, 0.f, 0.f, 0.f);
    float4 a3 = make_float4(0.f, 0.f, 0.f, 0.f);

    int j = js;
    for (; j + 7 < je; j += 8) {
        const int2 sw0 = __ldg(&csr_sw[j]);
        const int2 sw1 = __ldg(&csr_sw[j + 1]);
        const int2 sw2 = __ldg(&csr_sw[j + 2]);
        const int2 sw3 = __ldg(&csr_sw[j + 3]);
        const int2 sw4 = __ldg(&csr_sw[j + 4]);
        const int2 sw5 = __ldg(&csr_sw[j + 5]);
        const int2 sw6 = __ldg(&csr_sw[j + 6]);
        const int2 sw7 = __ldg(&csr_sw[j + 7]);
        const float w0 = dd * __int_as_float(sw0.y);
        const float w1 = dd * __int_as_float(sw1.y);
        const float w2 = dd * __int_as_float(sw2.y);
        const float w3 = dd * __int_as_float(sw3.y);
        const float w4 = dd * __int_as_float(sw4.y);
        const float w5 = dd * __int_as_float(sw5.y);
        const float w6 = dd * __int_as_float(sw6.y);
        const float w7 = dd * __int_as_float(sw7.y);
        const float4 v0 = h4_to_f4(h[sw0.x * 32 + lane]);
        const float4 v1 = h4_to_f4(h[sw1.x * 32 + lane]);
        const float4 v2 = h4_to_f4(h[sw2.x * 32 + lane]);
        const float4 v3 = h4_to_f4(h[sw3.x * 32 + lane]);
        const float4 v4 = h4_to_f4(h[sw4.x * 32 + lane]);
        const float4 v5 = h4_to_f4(h[sw5.x * 32 + lane]);
        const float4 v6 = h4_to_f4(h[sw6.x * 32 + lane]);
        const float4 v7 = h4_to_f4(h[sw7.x * 32 + lane]);
        GFMA(a0, v0, w0); GFMA(a1, v1, w1); GFMA(a2, v2, w2); GFMA(a3, v3, w3);
        GFMA(a0, v4, w4); GFMA(a1, v5, w5); GFMA(a2, v6, w6); GFMA(a3, v7, w7);
    }
    for (; j + 3 < je; j += 4) {
        const int2 sw0 = __ldg(&csr_sw[j]);
        const int2 sw1 = __ldg(&csr_sw[j + 1]);
        const int2 sw2 = __ldg(&csr_sw[j + 2]);
        const int2 sw3 = __ldg(&csr_sw[j + 3]);
        const float w0 = dd * __int_as_float(sw0.y);
        const float w1 = dd * __int_as_float(sw1.y);
        const float w2 = dd * __int_as_float(sw2.y);
        const float w3 = dd * __int_as_float(sw3.y);
        const float4 v0 = h4_to_f4(h[sw0.x * 32 + lane]);
        const float4 v1 = h4_to_f4(h[sw1.x * 32 + lane]);
        const float4 v2 = h4_to_f4(h[sw2.x * 32 + lane]);
        const float4 v3 = h4_to_f4(h[sw3.x * 32 + lane]);
        GFMA(a0, v0, w0); GFMA(a1, v1, w1); GFMA(a2, v2, w2); GFMA(a3, v3, w3);
    }
    for (; j < je; j++) {
        const int2 sw0 = __ldg(&csr_sw[j]);
        const float w0 = dd * __int_as_float(sw0.y);
        const float4 v0 = h4_to_f4(h[sw0.x * 32 + lane]);
        GFMA(a0, v0, w0);
    }
    a0.x += a1.x + a2.x + a3.x;
    a0.y += a1.y + a2.y + a3.y;
    a0.z += a1.z + a2.z + a3.z;
    a0.w += a1.w + a2.w + a3.w;

    if (MODE == 1) {
        const float4 b = __ldg(&reinterpret_cast<const float4*>(bias)[lane]);
        a0.x += b.x; a0.y += b.y; a0.z += b.z; a0.w += b.w;
    }
    out[node * 32 + lane] = a0;

    // fused importance head for t=1 nodes (final timestep output)
    if (MODE == 1 && node >= nN) {
        const float4 w = __ldg(&reinterpret_cast<const float4*>(Wc)[lane]);
        float s = a0.x * w.x + a0.y * w.y + a0.z * w.z + a0.w * w.w;
#pragma unroll
        for (int o = 16; o; o >>= 1) s += __shfl_xor_sync(0xffffffffu, s, o);
        if (lane == 0) imp[node - nN] = s + __ldg(bc);
    }
}

// ---------------------------------------------------------------------------
// Launch — batched over both timesteps; CSR build overlapped with GEMM1
// ---------------------------------------------------------------------------
extern "C" void kernel_launch(void* const* d_in, const int* in_sizes, int n_in,
                              void* d_out, int out_size)
{
    const float*        x_seq = (const float*)d_in[0];        // [2N, 128] contiguous
    const unsigned int* eraw  = (const unsigned int*)d_in[1]; // [T, 2, E] int32 or int64
    const float*        W1    = (const float*)d_in[2];
    const float*        b1    = (const float*)d_in[3];
    const float*        W2    = (const float*)d_in[4];
    const float*        b2    = (const float*)d_in[5];
    const float*        Wc    = (const float*)d_in[6];
    const float*        bc    = (const float*)d_in[7];

    const int N = in_sizes[0] / (TT * CDIM);
    const int E = in_sizes[1] / (TT * 2);
    const int totalE = TT * 2 * E;
    const int n2 = TT * N;

    float* out  = (float*)d_out;
    float* imp  = out;          // [N]
    float* outs = out + N;      // [2N,128] contiguous (out_t0 then out_t1)

    uint2* dh;  float4* dagg;  float* ddinv;
    int* dhist;  int* drowptr;  int* dcursor;  int2* dcsr;  int* dbsum;
    __nv_bfloat16* dwh; __nv_bfloat16* dwl;
    cudaGetSymbolAddress((void**)&dh,      g_h);
    cudaGetSymbolAddress((void**)&dagg,    g_agg);
    cudaGetSymbolAddress((void**)&ddinv,   g_dinv);
    cudaGetSymbolAddress((void**)&dhist,   g_hist);
    cudaGetSymbolAddress((void**)&drowptr, g_rowptr);
    cudaGetSymbolAddress((void**)&dcursor, g_cursor);
    cudaGetSymbolAddress((void**)&dcsr,    g_csr_sw);
    cudaGetSymbolAddress((void**)&dbsum,   g_bsum);
    cudaGetSymbolAddress((void**)&dwh,     g_wh);
    cudaGetSymbolAddress((void**)&dwl,     g_wl);

    static bool s_init = false;
    static cudaStream_t s_side = nullptr;
    static cudaEvent_t ev_fork = nullptr, ev_join = nullptr;
    if (!s_init) {
        cudaFuncSetAttribute(k_gemm_mma, cudaFuncAttributeMaxDynamicSharedMemorySize,
                             GEMM_SMEM);
        if (cudaStreamCreateWithFlags(&s_side, cudaStreamNonBlocking) != cudaSuccess)
            s_side = nullptr;
        if (s_side) {
            cudaEventCreateWithFlags(&ev_fork, cudaEventDisableTiming);
            cudaEventCreateWithFlags(&ev_join, cudaEventDisableTiming);
        }
        s_init = true;
    }

    const int TPB = 256;
    const int gGemm = (n2 + 63) / 64;
    const int gGath = (n2 + 7) / 8;
    const int g2E   = (2 * E + TPB - 1) / TPB;
    const int g2N   = (n2 + TPB - 1) / TPB;
    const int nb    = (n2 + 1023) / 1024;

    const bool fork = (s_side != nullptr);
    cudaStream_t sc = fork ? s_side : (cudaStream_t)0;

    // Edge dtype probe (main stream), then fork the CSR chain behind it.
    // Every side-stream launch must come AFTER the fork event so it is part
    // of the captured graph.
    k_detect<<<1, 32>>>(eraw, totalE);
    if (fork) {
        cudaEventRecord(ev_fork, 0);
        cudaStreamWaitEvent(s_side, ev_fork, 0);
    }

    // --- CSR build chain (side stream, fully captured) ---
    k_zero<<<g2N, TPB, 0, sc>>>(dhist, n2);
    k_hist2<<<g2E, TPB, 0, sc>>>(dhist, eraw, E, N);
    k_bsum<<<nb, TPB, 0, sc>>>(dhist, dbsum, n2);
    k_scanb<<<1, 128, 0, sc>>>(dbsum, drowptr, nb, n2);
    k_rowptr<<<nb, TPB, 0, sc>>>(dhist, dbsum, drowptr, dcursor, ddinv, n2);
    k_permute2<<<g2E, TPB, 0, sc>>>(eraw, dcursor, dcsr, ddinv, E, N);
    if (fork) cudaEventRecord(ev_join, s_side);

    // --- Main stream: W splits + conv1 GEMM (independent of CSR) ---
    k_wsplit<<<64, TPB>>>(W1, dwh, dwl);
    k_wsplit<<<64, TPB>>>(W2, dwh + CDIM * CDIM, dwl + CDIM * CDIM);
    k_gemm_mma<<<gGemm, TPB, GEMM_SMEM>>>(x_seq, dwh, dwl, b1, (__half*)dh, n2, 0);

    if (fork) cudaStreamWaitEvent(0, ev_join, 0);

    // conv1 aggregation, conv2 GEMM, conv2 aggregation + fused importance.
    k_gather<0><<<gGath, TPB>>>(dh, dagg, drowptr, dcsr, ddinv,
                                b1, n2, Wc, bc, imp, N);
    k_gemm_mma<<<gGemm, TPB, GEMM_SMEM>>>((const float*)dagg, dwh + CDIM * CDIM,
                                          dwl + CDIM * CDIM, b1, (__half*)dh, n2, 1);
    k_gather<1><<<gGath, TPB>>>(dh, (float4*)outs, drowptr, dcsr, ddinv,
                                b2, n2, Wc, bc, imp, N);
}

// round 15
// speedup vs baseline: 1.0495x; 1.0341x over previous
#include <cuda_runtime.h>
#include <cuda_bf16.h>
#include <cuda_fp16.h>
#include <cstdint>

// Problem constants (from reference): T=2, N=50000, E=800000, C=128
#define TT 2
#define MAXN 50000
#define MAXE 800000
#define CDIM 128

// Scratch (device globals: allocation-free rule). Everything batched over 2N/2E.
__device__ uint2  g_h[TT * MAXN * 32];          // 25.6 MB (GEMM product, fp16 rows, 2N)
__device__ float4 g_agg[TT * MAXN * (CDIM/4)];  // 51.2 MB (conv1 aggregation, fp32, 2N)
__device__ float  g_dinv[TT * MAXN];            // rsqrt(1 + deg)
__device__ int    g_hist[TT * MAXN];            // per-dst degree histogram
__device__ int    g_rowptr[TT * MAXN + 1];      // CSR row offsets (concatenated)
__device__ int    g_cursor[TT * MAXN];          // fill cursors for permute
__device__ int    g_csr_src[TT * MAXE];         // GLOBAL src id (t*N+s) per CSR slot
__device__ int    g_bsum[128];                  // per-1024-chunk sums for scan
__device__ int    g_is64;                       // 1 if input edge dtype is int64
__device__ __nv_bfloat16 g_wh[2][CDIM * CDIM];  // pre-split W (high)
__device__ __nv_bfloat16 g_wl[2][CDIM * CDIM];  // pre-split W (low)

// ---------------------------------------------------------------------------
// Edge-index dtype detection (raw buffer may be int32 or int64)
// ---------------------------------------------------------------------------
__global__ void k_detect(const unsigned int* __restrict__ raw, int total_elems) {
    if (blockIdx.x == 0 && threadIdx.x == 0) {
        int n = total_elems < 64 ? total_elems : 64;
        int all0 = 1;
        for (int i = 0; i < n; i++)
            if (raw[2 * i + 1] != 0u) { all0 = 0; break; }
        g_is64 = all0;
    }
}

__device__ __forceinline__ int load_idx(const unsigned int* raw, int pos, int is64) {
    return is64 ? (int)raw[2 * (size_t)pos] : (int)raw[pos];
}

// ---------------------------------------------------------------------------
// W split: W (f32) -> Wh + Wl (bf16), done once per weight matrix.
// ---------------------------------------------------------------------------
__global__ void k_wsplit(const float* __restrict__ W, __nv_bfloat16* __restrict__ H,
                         __nv_bfloat16* __restrict__ L) {
    const int i = blockIdx.x * blockDim.x + threadIdx.x;
    const float v = W[i];
    const __nv_bfloat16 h = __float2bfloat16(v);
    H[i] = h;
    L[i] = __float2bfloat16(v - __bfloat162float(h));
}

// ---------------------------------------------------------------------------
// Batched CSR build (both timesteps)
// ---------------------------------------------------------------------------
__global__ void k_zero(int* p, int n) {
    int i = blockIdx.x * blockDim.x + threadIdx.x;
    if (i < n) p[i] = 0;
}

__global__ void k_hist2(int* __restrict__ hist, const unsigned int* __restrict__ raw,
                        int E, int N) {
    int i = blockIdx.x * blockDim.x + threadIdx.x;
    if (i >= 2 * E) return;
    const int is64 = g_is64;
    const int t = (i >= E) ? 1 : 0;
    const int eid = i - t * E;
    const int d = load_idx(raw, t * 2 * E + E + eid, is64);
    atomicAdd(&hist[t * N + d], 1);
}

__global__ __launch_bounds__(256) void k_bsum(const int* __restrict__ hist,
                                              int* __restrict__ bsum, int n) {
    __shared__ int ws[8];
    const int tid = threadIdx.x;
    const int base = blockIdx.x * 1024;
    int s = 0;
#pragma unroll
    for (int k = 0; k < 4; k++) {
        int i = base + k * 256 + tid;
        if (i < n) s += hist[i];
    }
#pragma unroll
    for (int o = 16; o; o >>= 1) s += __shfl_xor_sync(0xffffffffu, s, o);
    if ((tid & 31) == 0) ws[tid >> 5] = s;
    __syncthreads();
    if (tid < 32) {
        int v = (tid < 8) ? ws[tid] : 0;
#pragma unroll
        for (int o = 4; o; o >>= 1) v += __shfl_xor_sync(0xffffffffu, v, o);
        if (tid == 0) bsum[blockIdx.x] = v;
    }
}

__global__ __launch_bounds__(128) void k_scanb(int* __restrict__ bsum,
                                               int* __restrict__ rowptr,
                                               int nb, int n2) {
    __shared__ int ws[4];
    const int tid = threadIdx.x, lane = tid & 31, wid = tid >> 5;
    int v = (tid < nb) ? bsum[tid] : 0;
    int x = v;
#pragma unroll
    for (int o = 1; o < 32; o <<= 1) {
        int u = __shfl_up_sync(0xffffffffu, x, o);
        if (lane >= o) x += u;
    }
    if (lane == 31) ws[wid] = x;
    __syncthreads();
    if (wid == 0) {
        int wv = (lane < 4) ? ws[lane] : 0;
        int y = wv;
#pragma unroll
        for (int o = 1; o < 4; o <<= 1) {
            int u = __shfl_up_sync(0xffffffffu, y, o);
            if (lane >= o) y += u;
        }
        if (lane < 4) ws[lane] = y - wv;
    }
    __syncthreads();
    const int excl = x - v + ws[wid];
    if (tid < nb) bsum[tid] = excl;
    if (tid == nb - 1) rowptr[n2] = excl + v;
}

__global__ __launch_bounds__(256) void k_rowptr(const int* __restrict__ hist,
                                                const int* __restrict__ boff,
                                                int* __restrict__ rowptr,
                                                int* __restrict__ cursor,
                                                float* __restrict__ dinv, int n) {
    __shared__ int wsum[8];
    const int tid = threadIdx.x, lane = tid & 31, wid = tid >> 5;
    const int i0 = blockIdx.x * 1024 + tid * 4;
    int v0 = (i0     < n) ? hist[i0]     : 0;
    int v1 = (i0 + 1 < n) ? hist[i0 + 1] : 0;
    int v2 = (i0 + 2 < n) ? hist[i0 + 2] : 0;
    int v3 = (i0 + 3 < n) ? hist[i0 + 3] : 0;
    const int t = v0 + v1 + v2 + v3;
    int x = t;
#pragma unroll
    for (int o = 1; o < 32; o <<= 1) {
        int u = __shfl_up_sync(0xffffffffu, x, o);
        if (lane >= o) x += u;
    }
    if (lane == 31) wsum[wid] = x;
    __syncthreads();
    if (wid == 0) {
        int wv = (lane < 8) ? wsum[lane] : 0;
        int y = wv;
#pragma unroll
        for (int o = 1; o < 8; o <<= 1) {
            int u = __shfl_up_sync(0xffffffffu, y, o);
            if (lane >= o) y += u;
        }
        if (lane < 8) wsum[lane] = y - wv;
    }
    __syncthreads();
    int e0 = (x - t) + wsum[wid] + boff[blockIdx.x];
    int e1 = e0 + v0, e2 = e1 + v1, e3 = e2 + v2;
    if (i0     < n) { rowptr[i0]     = e0; cursor[i0]     = e0; dinv[i0]     = rsqrtf(1.0f + (float)v0); }
    if (i0 + 1 < n) { rowptr[i0 + 1] = e1; cursor[i0 + 1] = e1; dinv[i0 + 1] = rsqrtf(1.0f + (float)v1); }
    if (i0 + 2 < n) { rowptr[i0 + 2] = e2; cursor[i0 + 2] = e2; dinv[i0 + 2] = rsqrtf(1.0f + (float)v2); }
    if (i0 + 3 < n) { rowptr[i0 + 3] = e3; cursor[i0 + 3] = e3; dinv[i0 + 3] = rsqrtf(1.0f + (float)v3); }
}

// Permute: csr_src gets GLOBAL src id (t*N + s); lean (no dinv read/write).
__global__ void k_permute2(const unsigned int* __restrict__ raw, int* __restrict__ cursor,
                           int* __restrict__ csr_src, int E, int N) {
    int i = blockIdx.x * blockDim.x + threadIdx.x;
    if (i >= 2 * E) return;
    const int is64 = g_is64;
    const int t = (i >= E) ? 1 : 0;
    const int eid = i - t * E;
    const int s = load_idx(raw, t * 2 * E + eid, is64);
    const int d = load_idx(raw, t * 2 * E + E + eid, is64);
    const int pos = atomicAdd(&cursor[t * N + d], 1);
    csr_src[pos] = t * N + s;
}

// ---------------------------------------------------------------------------
// Tensor-core GEMM: Yh[n,128] (fp16) = f(X)[n,128] (fp32) @ W[128,128]
// bf16 2-way split (3 MMA terms). W pre-split in global. M-tile 64.
// ---------------------------------------------------------------------------
#define SPAD 136
#define GEMM_SMEM ((2 * 64 + 2 * 128) * SPAD * 2)

__device__ __forceinline__ void store_split_a(__nv_bfloat16* H, __nv_bfloat16* L,
                                              int off, float4 v) {
    __nv_bfloat16 h0 = __float2bfloat16(v.x);
    __nv_bfloat16 h1 = __float2bfloat16(v.y);
    __nv_bfloat16 h2 = __float2bfloat16(v.z);
    __nv_bfloat16 h3 = __float2bfloat16(v.w);
    __nv_bfloat16 l0 = __float2bfloat16(v.x - __bfloat162float(h0));
    __nv_bfloat16 l1 = __float2bfloat16(v.y - __bfloat162float(h1));
    __nv_bfloat16 l2 = __float2bfloat16(v.z - __bfloat162float(h2));
    __nv_bfloat16 l3 = __float2bfloat16(v.w - __bfloat162float(h3));
    uint2 ph, pl;
    ph.x = (uint32_t)__bfloat16_as_ushort(h0) | ((uint32_t)__bfloat16_as_ushort(h1) << 16);
    ph.y = (uint32_t)__bfloat16_as_ushort(h2) | ((uint32_t)__bfloat16_as_ushort(h3) << 16);
    pl.x = (uint32_t)__bfloat16_as_ushort(l0) | ((uint32_t)__bfloat16_as_ushort(l1) << 16);
    pl.y = (uint32_t)__bfloat16_as_ushort(l2) | ((uint32_t)__bfloat16_as_ushort(l3) << 16);
    *reinterpret_cast<uint2*>(H + off) = ph;
    *reinterpret_cast<uint2*>(L + off) = pl;
}

#define LDSM_X4(r0, r1, r2, r3, addr)                                          \
    asm volatile("ldmatrix.sync.aligned.m8n8.x4.shared.b16 {%0,%1,%2,%3}, [%4];" \
                 : "=r"(r0), "=r"(r1), "=r"(r2), "=r"(r3) : "r"(addr))

#define LDSM_X4T(r0, r1, r2, r3, addr)                                         \
    asm volatile("ldmatrix.sync.aligned.m8n8.x4.trans.shared.b16 {%0,%1,%2,%3}, [%4];" \
                 : "=r"(r0), "=r"(r1), "=r"(r2), "=r"(r3) : "r"(addr))

#define MMA16816(C, a0, a1, a2, a3, b0, b1)                                    \
    asm volatile("mma.sync.aligned.m16n8k16.row.col.f32.bf16.bf16.f32 "        \
                 "{%0,%1,%2,%3}, {%4,%5,%6,%7}, {%8,%9}, {%0,%1,%2,%3};"       \
                 : "+f"(C[0]), "+f"(C[1]), "+f"(C[2]), "+f"(C[3])              \
                 : "r"(a0), "r"(a1), "r"(a2), "r"(a3), "r"(b0), "r"(b1))

__global__ __launch_bounds__(256) void k_gemm_mma(
    const float* __restrict__ X,
    const __nv_bfloat16* __restrict__ Whg, const __nv_bfloat16* __restrict__ Wlg,
    const float* __restrict__ bias, __half* __restrict__ Y, int nrows, int mode)
{
    extern __shared__ __nv_bfloat16 sm[];
    __nv_bfloat16* Ah = sm;                       //  64 x SPAD
    __nv_bfloat16* Al = Ah + 64 * SPAD;           //  64 x SPAD
    __nv_bfloat16* Wh = Al + 64 * SPAD;           // 128 x SPAD
    __nv_bfloat16* Wl = Wh + 128 * SPAD;          // 128 x SPAD

    const int tid = threadIdx.x;
    const int lane = tid & 31, wid = tid >> 5;
    const int rowBase = blockIdx.x * 64;

#pragma unroll
    for (int it = 0; it < 8; it++) {
        const int idx = it * 256 + tid;
        const int row = idx >> 4;
        const int c8  = (idx & 15) * 8;
        *reinterpret_cast<uint4*>(Wh + row * SPAD + c8) =
            reinterpret_cast<const uint4*>(Whg)[idx];
        *reinterpret_cast<uint4*>(Wl + row * SPAD + c8) =
            reinterpret_cast<const uint4*>(Wlg)[idx];
    }
#pragma unroll
    for (int it = 0; it < 8; it++) {
        const int idx = it * 256 + tid;
        const int row = idx >> 5;
        const int c4  = idx & 31;
        const int grow = rowBase + row;
        float4 v = make_float4(0.f, 0.f, 0.f, 0.f);
        if (grow < nrows) v = reinterpret_cast<const float4*>(X)[grow * 32 + c4];
        if (mode == 1) {
            const float4 b = reinterpret_cast<const float4*>(bias)[c4];
            v.x = fmaxf(v.x + b.x, 0.f);
            v.y = fmaxf(v.y + b.y, 0.f);
            v.z = fmaxf(v.z + b.z, 0.f);
            v.w = fmaxf(v.w + b.w, 0.f);
        }
        store_split_a(Ah, Al, row * SPAD + c4 * 4, v);
    }
    __syncthreads();

    const uint32_t sb = (uint32_t)__cvta_generic_to_shared(sm);
    const uint32_t AHALF = 64 * SPAD * 2;
    const uint32_t WBASE = 2u * AHALF;
    const uint32_t WHALF = 128 * SPAD * 2;
    const int sub = lane >> 3, li = lane & 7;
    const int wm = wid & 3;
    const int wn = wid >> 2;
    const int arow = wm * 16 + ((sub & 1) << 3) + li;
    const int acol0 = (sub >> 1) << 3;
    const int bkrow0 = ((sub & 1) << 3) + li;
    const int bncol0 = wn * 64 + ((sub >> 1) << 3);

    float acc[8][4];
#pragma unroll
    for (int t = 0; t < 8; t++)
#pragma unroll
        for (int c = 0; c < 4; c++) acc[t][c] = 0.f;

    for (int k0 = 0; k0 < 128; k0 += 16) {
        uint32_t aaddr = sb + (uint32_t)((arow * SPAD + k0 + acol0) * 2);
        uint32_t ah0, ah1, ah2, ah3, al0, al1, al2, al3;
        LDSM_X4(ah0, ah1, ah2, ah3, aaddr);
        LDSM_X4(al0, al1, al2, al3, aaddr + AHALF);

#pragma unroll
        for (int np = 0; np < 4; np++) {
            uint32_t baddr = sb + WBASE +
                (uint32_t)(((k0 + bkrow0) * SPAD + np * 16 + bncol0) * 2);
            uint32_t bh0, bh1, bh2, bh3, bl0, bl1, bl2, bl3;
            LDSM_X4T(bh0, bh1, bh2, bh3, baddr);
            LDSM_X4T(bl0, bl1, bl2, bl3, baddr + WHALF);
            const int t0 = np * 2, t1 = t0 + 1;
            MMA16816(acc[t0], ah0, ah1, ah2, ah3, bh0, bh1);
            MMA16816(acc[t0], al0, al1, al2, al3, bh0, bh1);
            MMA16816(acc[t0], ah0, ah1, ah2, ah3, bl0, bl1);
            MMA16816(acc[t1], ah0, ah1, ah2, ah3, bh2, bh3);
            MMA16816(acc[t1], al0, al1, al2, al3, bh2, bh3);
            MMA16816(acc[t1], ah0, ah1, ah2, ah3, bl2, bl3);
        }
    }

    const int r0 = rowBase + wm * 16 + (lane >> 2);
    const int c0 = wn * 64 + (lane & 3) * 2;
#pragma unroll
    for (int nt = 0; nt < 8; nt++) {
        const int col = c0 + nt * 8;
        if (r0 < nrows)
            *reinterpret_cast<__half2*>(&Y[r0 * 128 + col]) =
                __floats2half2_rn(acc[nt][0], acc[nt][1]);
        if (r0 + 8 < nrows)
            *reinterpret_cast<__half2*>(&Y[(r0 + 8) * 128 + col]) =
                __floats2half2_rn(acc[nt][2], acc[nt][3]);
    }
}

// ---------------------------------------------------------------------------
// CSR gather (R11 shape): one warp per node, uint2 (8B/lane) fp16 rows,
// unroll x8 for MLP, separate csr_src + dinv gathers (latency-hidden).
// MODE 1 adds bias b2 and fuses the importance head for nodes >= nN.
// ---------------------------------------------------------------------------
__device__ __forceinline__ float4 h4_to_f4(uint2 u) {
    const __half2 a = *reinterpret_cast<__half2*>(&u.x);
    const __half2 b = *reinterpret_cast<__half2*>(&u.y);
    const float2 fa = __half22float2(a), fb = __half22float2(b);
    return make_float4(fa.x, fa.y, fb.x, fb.y);
}

#define GFMA(A, V, W) \
    A.x = fmaf(V.x, W, A.x); A.y = fmaf(V.y, W, A.y); \
    A.z = fmaf(V.z, W, A.z); A.w = fmaf(V.w, W, A.w);

template <int MODE>
__global__ __launch_bounds__(256) void k_gather(
    const uint2* __restrict__ h, float4* __restrict__ out,
    const int* __restrict__ rowptr, const int* __restrict__ csr_src,
    const float* __restrict__ dinv, const float* __restrict__ bias, int n,
    const float* __restrict__ Wc, const float* __restrict__ bc,
    float* __restrict__ imp, int nN)
{
    const int node = blockIdx.x * 8 + (threadIdx.x >> 5);
    if (node >= n) return;
    const int lane = threadIdx.x & 31;

    const float dd = __ldg(&dinv[node]);
    const int js = __ldg(&rowptr[node]);
    const int je = __ldg(&rowptr[node + 1]);

    const float4 v = h4_to_f4(h[node * 32 + lane]);
    const float sl = dd * dd;
    float4 a0 = make_float4(v.x * sl, v.y * sl, v.z * sl, v.w * sl);
    float4 a1 = make_float4(0.f, 0.f, 0.f, 0.f);
    float4 a2 = make_float4(0.f, 0.f, 0.f, 0.f);
    float4 a3 = make_float4(0.f, 0.f, 0.f, 0.f);

    int j = js;
    for (; j + 7 < je; j += 8) {
        const int s0 = __ldg(&csr_src[j]);
        const int s1 = __ldg(&csr_src[j + 1]);
        const int s2 = __ldg(&csr_src[j + 2]);
        const int s3 = __ldg(&csr_src[j + 3]);
        const int s4 = __ldg(&csr_src[j + 4]);
        const int s5 = __ldg(&csr_src[j + 5]);
        const int s6 = __ldg(&csr_src[j + 6]);
        const int s7 = __ldg(&csr_src[j + 7]);
        const float w0 = dd * __ldg(&dinv[s0]);
        const float w1 = dd * __ldg(&dinv[s1]);
        const float w2 = dd * __ldg(&dinv[s2]);
        const float w3 = dd * __ldg(&dinv[s3]);
        const float w4 = dd * __ldg(&dinv[s4]);
        const float w5 = dd * __ldg(&dinv[s5]);
        const float w6 = dd * __ldg(&dinv[s6]);
        const float w7 = dd * __ldg(&dinv[s7]);
        const float4 v0 = h4_to_f4(h[s0 * 32 + lane]);
        const float4 v1 = h4_to_f4(h[s1 * 32 + lane]);
        const float4 v2 = h4_to_f4(h[s2 * 32 + lane]);
        const float4 v3 = h4_to_f4(h[s3 * 32 + lane]);
        const float4 v4 = h4_to_f4(h[s4 * 32 + lane]);
        const float4 v5 = h4_to_f4(h[s5 * 32 + lane]);
        const float4 v6 = h4_to_f4(h[s6 * 32 + lane]);
        const float4 v7 = h4_to_f4(h[s7 * 32 + lane]);
        GFMA(a0, v0, w0); GFMA(a1, v1, w1); GFMA(a2, v2, w2); GFMA(a3, v3, w3);
        GFMA(a0, v4, w4); GFMA(a1, v5, w5); GFMA(a2, v6, w6); GFMA(a3, v7, w7);
    }
    for (; j + 3 < je; j += 4) {
        const int s0 = __ldg(&csr_src[j]);
        const int s1 = __ldg(&csr_src[j + 1]);
        const int s2 = __ldg(&csr_src[j + 2]);
        const int s3 = __ldg(&csr_src[j + 3]);
        const float w0 = dd * __ldg(&dinv[s0]);
        const float w1 = dd * __ldg(&dinv[s1]);
        const float w2 = dd * __ldg(&dinv[s2]);
        const float w3 = dd * __ldg(&dinv[s3]);
        const float4 v0 = h4_to_f4(h[s0 * 32 + lane]);
        const float4 v1 = h4_to_f4(h[s1 * 32 + lane]);
        const float4 v2 = h4_to_f4(h[s2 * 32 + lane]);
        const float4 v3 = h4_to_f4(h[s3 * 32 + lane]);
        GFMA(a0, v0, w0); GFMA(a1, v1, w1); GFMA(a2, v2, w2); GFMA(a3, v3, w3);
    }
    for (; j < je; j++) {
        const int s0 = __ldg(&csr_src[j]);
        const float w0 = dd * __ldg(&dinv[s0]);
        const float4 v0 = h4_to_f4(h[s0 * 32 + lane]);
        GFMA(a0, v0, w0);
    }
    a0.x += a1.x + a2.x + a3.x;
    a0.y += a1.y + a2.y + a3.y;
    a0.z += a1.z + a2.z + a3.z;
    a0.w += a1.w + a2.w + a3.w;

    if (MODE == 1) {
        const float4 b = __ldg(&reinterpret_cast<const float4*>(bias)[lane]);
        a0.x += b.x; a0.y += b.y; a0.z += b.z; a0.w += b.w;
    }
    out[node * 32 + lane] = a0;

    // fused importance head for t=1 nodes (final timestep output)
    if (MODE == 1 && node >= nN) {
        const float4 w = __ldg(&reinterpret_cast<const float4*>(Wc)[lane]);
        float s = a0.x * w.x + a0.y * w.y + a0.z * w.z + a0.w * w.w;
#pragma unroll
        for (int o = 16; o; o >>= 1) s += __shfl_xor_sync(0xffffffffu, s, o);
        if (lane == 0) imp[node - nN] = s + __ldg(bc);
    }
}

// ---------------------------------------------------------------------------
// Launch — batched over both timesteps; CSR build overlapped with GEMM1
// ---------------------------------------------------------------------------
extern "C" void kernel_launch(void* const* d_in, const int* in_sizes, int n_in,
                              void* d_out, int out_size)
{
    const float*        x_seq = (const float*)d_in[0];        // [2N, 128] contiguous
    const unsigned int* eraw  = (const unsigned int*)d_in[1]; // [T, 2, E] int32 or int64
    const float*        W1    = (const float*)d_in[2];
    const float*        b1    = (const float*)d_in[3];
    const float*        W2    = (const float*)d_in[4];
    const float*        b2    = (const float*)d_in[5];
    const float*        Wc    = (const float*)d_in[6];
    const float*        bc    = (const float*)d_in[7];

    const int N = in_sizes[0] / (TT * CDIM);
    const int E = in_sizes[1] / (TT * 2);
    const int totalE = TT * 2 * E;
    const int n2 = TT * N;

    float* out  = (float*)d_out;
    float* imp  = out;          // [N]
    float* outs = out + N;      // [2N,128] contiguous (out_t0 then out_t1)

    uint2* dh;  float4* dagg;  float* ddinv;
    int* dhist;  int* drowptr;  int* dcursor;  int* dcsr;  int* dbsum;
    __nv_bfloat16* dwh; __nv_bfloat16* dwl;
    cudaGetSymbolAddress((void**)&dh,      g_h);
    cudaGetSymbolAddress((void**)&dagg,    g_agg);
    cudaGetSymbolAddress((void**)&ddinv,   g_dinv);
    cudaGetSymbolAddress((void**)&dhist,   g_hist);
    cudaGetSymbolAddress((void**)&drowptr, g_rowptr);
    cudaGetSymbolAddress((void**)&dcursor, g_cursor);
    cudaGetSymbolAddress((void**)&dcsr,    g_csr_src);
    cudaGetSymbolAddress((void**)&dbsum,   g_bsum);
    cudaGetSymbolAddress((void**)&dwh,     g_wh);
    cudaGetSymbolAddress((void**)&dwl,     g_wl);

    static bool s_init = false;
    static cudaStream_t s_side = nullptr;
    static cudaEvent_t ev_fork = nullptr, ev_join = nullptr;
    if (!s_init) {
        cudaFuncSetAttribute(k_gemm_mma, cudaFuncAttributeMaxDynamicSharedMemorySize,
                             GEMM_SMEM);
        if (cudaStreamCreateWithFlags(&s_side, cudaStreamNonBlocking) != cudaSuccess)
            s_side = nullptr;
        if (s_side) {
            cudaEventCreateWithFlags(&ev_fork, cudaEventDisableTiming);
            cudaEventCreateWithFlags(&ev_join, cudaEventDisableTiming);
        }
        s_init = true;
    }

    const int TPB = 256;
    const int gGemm = (n2 + 63) / 64;
    const int gGath = (n2 + 7) / 8;
    const int g2E   = (2 * E + TPB - 1) / TPB;
    const int g2N   = (n2 + TPB - 1) / TPB;
    const int nb    = (n2 + 1023) / 1024;

    const bool fork = (s_side != nullptr);
    cudaStream_t sc = fork ? s_side : (cudaStream_t)0;

    // Edge dtype probe (main stream), then fork the CSR chain behind it.
    // Every side-stream launch must come AFTER the fork event so it is part
    // of the captured graph.
    k_detect<<<1, 32>>>(eraw, totalE);
    if (fork) {
        cudaEventRecord(ev_fork, 0);
        cudaStreamWaitEvent(s_side, ev_fork, 0);
    }

    // --- CSR build chain (side stream, fully captured) ---
    k_zero<<<g2N, TPB, 0, sc>>>(dhist, n2);
    k_hist2<<<g2E, TPB, 0, sc>>>(dhist, eraw, E, N);
    k_bsum<<<nb, TPB, 0, sc>>>(dhist, dbsum, n2);
    k_scanb<<<1, 128, 0, sc>>>(dbsum, drowptr, nb, n2);
    k_rowptr<<<nb, TPB, 0, sc>>>(dhist, dbsum, drowptr, dcursor, ddinv, n2);
    k_permute2<<<g2E, TPB, 0, sc>>>(eraw, dcursor, dcsr, E, N);
    if (fork) cudaEventRecord(ev_join, s_side);

    // --- Main stream: W splits + conv1 GEMM (independent of CSR) ---
    k_wsplit<<<64, TPB>>>(W1, dwh, dwl);
    k_wsplit<<<64, TPB>>>(W2, dwh + CDIM * CDIM, dwl + CDIM * CDIM);
    k_gemm_mma<<<gGemm, TPB, GEMM_SMEM>>>(x_seq, dwh, dwl, b1, (__half*)dh, n2, 0);

    if (fork) cudaStreamWaitEvent(0, ev_join, 0);

    // conv1 aggregation, conv2 GEMM, conv2 aggregation + fused importance.
    k_gather<0><<<gGath, TPB>>>(dh, dagg, drowptr, dcsr, ddinv,
                                b1, n2, Wc, bc, imp, N);
    k_gemm_mma<<<gGemm, TPB, GEMM_SMEM>>>((const float*)dagg, dwh + CDIM * CDIM,
                                          dwl + CDIM * CDIM, b1, (__half*)dh, n2, 1);
    k_gather<1><<<gGath, TPB>>>(dh, (float4*)outs, drowptr, dcsr, ddinv,
                                b2, n2, Wc, bc, imp, N);
}